// round 2
// baseline (speedup 1.0000x reference)
#include <cuda_runtime.h>
#include <cstdint>

// VectorQuantizer: encodings [32,64,64,64] f32 (B,D,H,W), codebook [64,512] f32.
// For each of 131072 spatial vectors (length D=64), find nearest of K=512
// codewords by L2, emit that codeword back in [B,D,H,W] layout.

#define Dv 64
#define Kv 512
#define CB_STRIDE 68          // padded smem row stride (floats): 68*4=272B, 16B aligned
#define THREADS 512
#define HW 4096               // 64*64

// ---- packed f32x2 helpers (Blackwell dual-FP32 pipe) ----
__device__ __forceinline__ unsigned long long ffma2(unsigned long long a, unsigned long long b,
                                                    unsigned long long c) {
    unsigned long long d;
    asm("fma.rn.f32x2 %0, %1, %2, %3;" : "=l"(d) : "l"(a), "l"(b), "l"(c));
    return d;
}
__device__ __forceinline__ unsigned long long fadd2(unsigned long long a, unsigned long long b) {
    unsigned long long d;
    asm("add.rn.f32x2 %0, %1, %2;" : "=l"(d) : "l"(a), "l"(b));
    return d;
}
__device__ __forceinline__ float lo2(unsigned long long a) {
    return __uint_as_float((unsigned)(a & 0xffffffffULL));
}
__device__ __forceinline__ float hi2(unsigned long long a) {
    return __uint_as_float((unsigned)(a >> 32));
}
__device__ __forceinline__ unsigned long long pack2(float l, float h) {
    return ((unsigned long long)__float_as_uint(h) << 32) | (unsigned long long)__float_as_uint(l);
}

extern __shared__ float smem_dyn[];

__global__ void __launch_bounds__(THREADS)
vq_kernel(const float* __restrict__ enc, const float* __restrict__ cb,
          float* __restrict__ out, long long n_rows) {
    float* cbT = smem_dyn;                    // [512][68] transposed, padded
    float* ee  = smem_dyn + Kv * CB_STRIDE;   // [512] codeword norms

    const int tid = threadIdx.x;

    // ---- Stage codebook transposed into smem (coalesced gmem read) ----
    for (int i = tid; i < Dv * Kv; i += THREADS) {
        int d = i >> 9;       // i / 512
        int j = i & 511;      // i % 512
        cbT[j * CB_STRIDE + d] = cb[i];
    }
    __syncthreads();

    // ---- Per-codeword squared norms ----
    for (int j = tid; j < Kv; j += THREADS) {
        const float* row = cbT + j * CB_STRIDE;
        float s = 0.0f;
#pragma unroll
        for (int d = 0; d < Dv; d++) s = fmaf(row[d], row[d], s);
        ee[j] = s;
    }
    __syncthreads();

    // ---- Each thread owns one spatial vector ----
    const long long row = (long long)blockIdx.x * THREADS + tid;
    if (row >= n_rows) return;
    const int b  = (int)(row >> 12);   // row / 4096
    const int hw = (int)(row & 4095);
    const float* xptr = enc + (long long)b * Dv * HW + hw;

    // Load x into registers (warp-coalesced per d); pack pairs for f32x2.
    unsigned long long x2[Dv / 2];
    float xx = 0.0f;
#pragma unroll
    for (int i = 0; i < Dv / 2; i++) {
        float a = xptr[(2 * i + 0) * HW];
        float c = xptr[(2 * i + 1) * HW];
        xx = fmaf(a, a, xx);
        xx = fmaf(c, c, xx);
        x2[i] = pack2(a, c);
    }

    // ---- Argmin over 512 codewords ----
    float best = 3.4028235e38f;
    int bestj = 0;
    for (int j = 0; j < Kv; j++) {
        const ulonglong2* crow = (const ulonglong2*)(cbT + j * CB_STRIDE);
        unsigned long long acc0 = 0ULL, acc1 = 0ULL, acc2 = 0ULL, acc3 = 0ULL;
#pragma unroll
        for (int i = 0; i < 16; i += 2) {
            ulonglong2 v0 = crow[i + 0];     // 16B broadcast LDS
            ulonglong2 v1 = crow[i + 1];
            acc0 = ffma2(x2[2 * i + 0], v0.x, acc0);
            acc1 = ffma2(x2[2 * i + 1], v0.y, acc1);
            acc2 = ffma2(x2[2 * i + 2], v1.x, acc2);
            acc3 = ffma2(x2[2 * i + 3], v1.y, acc3);
        }
        unsigned long long s = fadd2(fadd2(acc0, acc1), fadd2(acc2, acc3));
        float mm = __fadd_rn(lo2(s), hi2(s));
        // Replicate reference rounding structure: (xx - 2*mm) + ee, no FMA fusion.
        float dist = __fadd_rn(__fsub_rn(xx, __fmul_rn(2.0f, mm)), ee[j]);
        if (dist < best) { best = dist; bestj = j; }  // strict < => tie -> lowest index
    }

    // ---- Write selected codeword back in [B,D,H,W] layout (coalesced per d) ----
    const float* q = cbT + bestj * CB_STRIDE;
    float* optr = out + (long long)b * Dv * HW + hw;
#pragma unroll
    for (int d = 0; d < Dv; d++) optr[d * HW] = q[d];
}

extern "C" void kernel_launch(void* const* d_in, const int* in_sizes, int n_in,
                              void* d_out, int out_size) {
    const float* enc = (const float*)d_in[0];   // [32,64,64,64]
    const float* cb  = (const float*)d_in[1];   // [64,512]
    float* out = (float*)d_out;

    const int smem_bytes = (Kv * CB_STRIDE + Kv) * (int)sizeof(float);  // 141312
    cudaFuncSetAttribute(vq_kernel, cudaFuncAttributeMaxDynamicSharedMemorySize, smem_bytes);

    const long long n_rows = (long long)out_size / Dv;   // 131072 for the reference shapes
    const int blocks = (int)((n_rows + THREADS - 1) / THREADS);
    vq_kernel<<<blocks, THREADS, smem_bytes>>>(enc, cb, out, n_rows);
}

// round 3
// speedup vs baseline: 1.2637x; 1.2637x over previous
#include <cuda_runtime.h>
#include <cstdint>

// VectorQuantizer: encodings [32,64,64,64] f32 (B,D,H,W), codebook [64,512] f32.
// Register-tiled fused GEMM + argmin + gather.
//   block = 256 rows x all 512 codewords (8 tiles of 64), 256 threads
//   thread = 8 rows x 8 codewords (f32x2-packed over codeword pairs)

#define Dv 64
#define Kv 512
#define HW 4096
#define MB 256          // rows per block
#define KT 64           // codewords per smem tile
#define NT (Kv / KT)    // 8 tiles
#define THREADS 256

// ---- packed f32x2 helpers ----
__device__ __forceinline__ unsigned long long ffma2(unsigned long long a, unsigned long long b,
                                                    unsigned long long c) {
    unsigned long long d;
    asm("fma.rn.f32x2 %0, %1, %2, %3;" : "=l"(d) : "l"(a), "l"(b), "l"(c));
    return d;
}
__device__ __forceinline__ unsigned long long dup2(float v) {
    unsigned long long d;
    unsigned u = __float_as_uint(v);
    asm("mov.b64 %0, {%1, %1};" : "=l"(d) : "r"(u));
    return d;
}
__device__ __forceinline__ void unpack2(unsigned long long a, float& l, float& h) {
    unsigned lo, hi;
    asm("mov.b64 {%0, %1}, %2;" : "=r"(lo), "=r"(hi) : "l"(a));
    l = __uint_as_float(lo);
    h = __uint_as_float(hi);
}

extern __shared__ float sm[];

__global__ void __launch_bounds__(THREADS, 2)
vq_kernel(const float* __restrict__ enc, const float* __restrict__ cb,
          float* __restrict__ out) {
    float* xs   = sm;                    // [64][256] x tile, d-major
    float* cbs  = xs + Dv * MB;          // [2][64][64] codebook tiles, d-major
    float* eesh = cbs + 2 * Dv * KT;     // [512] codeword norms
    float* xxsh = eesh + Kv;             // [256] row norms
    int*   bjsh = (int*)(xxsh + MB);     // [256] winning index per row

    const int tid = threadIdx.x;
    const int tr  = tid >> 3;            // 0..31 : row group (8 rows)
    const int tc  = tid & 7;             // 0..7  : cw group  (8 cws)

    const long long row0 = (long long)blockIdx.x * MB;
    const int b   = (int)(row0 >> 12);   // 4096 rows per batch image
    const int hw0 = (int)(row0 & 4095);
    const float* encb = enc + (long long)b * (Dv * HW) + hw0;

    // ---- stage x tile: xs[d][r] = enc[b][d][hw0+r] (coalesced) ----
    for (int i = tid; i < Dv * MB; i += THREADS) {
        int d = i >> 8, r = i & 255;
        xs[i] = encb[d * HW + r];
    }

    // ---- codeword norms (sequential fmaf over d, validated vs reference) ----
    for (int j = tid; j < Kv; j += THREADS) {
        float e = 0.0f;
#pragma unroll 8
        for (int d = 0; d < Dv; d++) {
            float c = cb[d * Kv + j];
            e = fmaf(c, c, e);
        }
        eesh[j] = e;
    }
    __syncthreads();

    // ---- row norms from smem (sequential fmaf over d) ----
    {
        float v = 0.0f;
#pragma unroll 8
        for (int d = 0; d < Dv; d++) {
            float a = xs[d * MB + tid];
            v = fmaf(a, a, v);
        }
        xxsh[tid] = v;
    }

    // ---- preload codebook tile 0 ----
    for (int i = tid; i < Dv * KT; i += THREADS) {
        int d = i >> 6, c = i & 63;
        cbs[i] = cb[d * Kv + c];
    }
    __syncthreads();

    // per-thread state for its 8 rows
    float xx[8];
#pragma unroll
    for (int r = 0; r < 8; r++) xx[r] = xxsh[tr * 8 + r];
    float best[8];
    int   bestj[8];
#pragma unroll
    for (int r = 0; r < 8; r++) { best[r] = 3.4028235e38f; bestj[r] = 0; }

    // ---- main loop over codeword tiles ----
    for (int t = 0; t < NT; t++) {
        const float* cbuf = cbs + (t & 1) * (Dv * KT);

        // prefetch next tile into the other buffer
        if (t + 1 < NT) {
            float* nb = cbs + ((t + 1) & 1) * (Dv * KT);
            for (int i = tid; i < Dv * KT; i += THREADS) {
                int d = i >> 6, c = i & 63;
                nb[i] = cb[d * Kv + (t + 1) * KT + c];
            }
        }

        // acc[r][cp]: 8 rows x 4 cw-pairs (f32x2), sequential over d
        unsigned long long acc[8][4];
#pragma unroll
        for (int r = 0; r < 8; r++)
#pragma unroll
            for (int cp = 0; cp < 4; cp++) acc[r][cp] = 0ULL;

        const float* xp = xs + tr * 8;
        const float* cp0 = cbuf + tc * 8;

#pragma unroll 2
        for (int d = 0; d < Dv; d++) {
            // 8 row values (two 16B broadcasts, conflict-free)
            ulonglong2 xa = *(const ulonglong2*)(xp + d * MB);
            ulonglong2 xb = *(const ulonglong2*)(xp + d * MB + 4);
            float xr[8];
            unpack2(xa.x, xr[0], xr[1]);
            unpack2(xa.y, xr[2], xr[3]);
            unpack2(xb.x, xr[4], xr[5]);
            unpack2(xb.y, xr[6], xr[7]);
            // 8 cw values as 4 packed pairs (two 16B loads, conflict-free)
            ulonglong2 ca = *(const ulonglong2*)(cp0 + d * KT);
            ulonglong2 cbp = *(const ulonglong2*)(cp0 + d * KT + 4);
            unsigned long long cw[4] = {ca.x, ca.y, cbp.x, cbp.y};
#pragma unroll
            for (int r = 0; r < 8; r++) {
                unsigned long long xd = dup2(xr[r]);
#pragma unroll
                for (int c = 0; c < 4; c++)
                    acc[r][c] = ffma2(xd, cw[c], acc[r][c]);
            }
        }

        // epilogue for this tile: dist = fl(fl(xx - fl(2*mm)) + ee), strict <
        int jbase = t * KT + tc * 8;
#pragma unroll
        for (int c = 0; c < 4; c++) {
            int j0 = jbase + 2 * c;
            float ee0 = eesh[j0];
            float ee1 = eesh[j0 + 1];
#pragma unroll
            for (int r = 0; r < 8; r++) {
                float m0, m1;
                unpack2(acc[r][c], m0, m1);
                float d0 = __fadd_rn(__fsub_rn(xx[r], __fmul_rn(2.0f, m0)), ee0);
                float d1 = __fadd_rn(__fsub_rn(xx[r], __fmul_rn(2.0f, m1)), ee1);
                if (d0 < best[r]) { best[r] = d0; bestj[r] = j0; }
                if (d1 < best[r]) { best[r] = d1; bestj[r] = j0 + 1; }
            }
        }
        __syncthreads();   // tile consumed; next tile fully staged
    }

    // ---- reduce argmin across the 8 cw-threads (lanes tc=0..7 of same tr) ----
#pragma unroll
    for (int r = 0; r < 8; r++) {
        float bd = best[r];
        int   bj = bestj[r];
#pragma unroll
        for (int off = 1; off < 8; off <<= 1) {
            float od = __shfl_xor_sync(0xffffffffu, bd, off);
            int   oj = __shfl_xor_sync(0xffffffffu, bj, off);
            if (od < bd || (od == bd && oj < bj)) { bd = od; bj = oj; }
        }
        if (tc == 0) bjsh[tr * 8 + r] = bj;
    }
    __syncthreads();

    // ---- gather winning codeword, write [B,D,H,W] coalesced ----
    float* outb = out + (long long)b * (Dv * HW) + hw0;
    int myj = bjsh[tid];   // this thread owns row `tid`
#pragma unroll 4
    for (int d = 0; d < Dv; d++) {
        outb[d * HW + tid] = __ldg(&cb[d * Kv + myj]);
    }
}

extern "C" void kernel_launch(void* const* d_in, const int* in_sizes, int n_in,
                              void* d_out, int out_size) {
    const float* enc = (const float*)d_in[0];   // [32,64,64,64]
    const float* cb  = (const float*)d_in[1];   // [64,512]
    float* out = (float*)d_out;

    const int smem_bytes = (Dv * MB + 2 * Dv * KT + Kv + MB) * (int)sizeof(float)
                         + MB * (int)sizeof(int);      // 102400 B
    cudaFuncSetAttribute(vq_kernel, cudaFuncAttributeMaxDynamicSharedMemorySize, smem_bytes);

    const long long n_rows = (long long)out_size / Dv;      // 131072
    const int blocks = (int)((n_rows + MB - 1) / MB);       // 512
    vq_kernel<<<blocks, THREADS, smem_bytes>>>(enc, cb, out);
}